// round 9
// baseline (speedup 1.0000x reference)
#include <cuda_runtime.h>

// Problem constants
#define BB 256      // batch
#define TT 2000     // seq len
#define HH 64       // hidden
#define G4 256      // 4*H
#define VV 2000     // vocab

// Scratch (allocation-free rule: __device__ globals)
__device__ float g_proj[(size_t)VV * G4];   // [v][j] fp32 (gate-prescaled), 2 MB
__device__ float g_hf[BB * HH];

typedef unsigned long long u64;

__device__ __forceinline__ u64 fma2(u64 a, u64 b, u64 c) {
    u64 d;
    asm("fma.rn.f32x2 %0, %1, %2, %3;" : "=l"(d) : "l"(a), "l"(b), "l"(c));
    return d;
}
__device__ __forceinline__ u64 add2(u64 a, u64 b) {
    u64 d;
    asm("add.rn.f32x2 %0, %1, %2;" : "=l"(d) : "l"(a), "l"(b));
    return d;
}
__device__ __forceinline__ u64 pack2(float lo, float hi) {
    u64 d;
    asm("mov.b64 %0, {%1, %2};" : "=l"(d) : "f"(lo), "f"(hi));
    return d;
}
__device__ __forceinline__ float hsum2(u64 a) {
    float lo, hi;
    asm("mov.b64 {%0, %1}, %2;" : "=f"(lo), "=f"(hi) : "l"(a));
    return lo + hi;
}
__device__ __forceinline__ float ex2_(float x) {
    float r; asm("ex2.approx.f32 %0, %1;" : "=f"(r) : "f"(x)); return r;
}
__device__ __forceinline__ float rcp_(float x) {
    float r; asm("rcp.approx.f32 %0, %1;" : "=f"(r) : "f"(x)); return r;
}
__device__ __forceinline__ float tanha_(float x) {
    float r; asm("tanh.approx.f32 %0, %1;" : "=f"(r) : "f"(x)); return r;
}
__device__ __forceinline__ float sigmoid_(float x) {
    return rcp_(1.0f + ex2_(-1.4426950408889634f * x));
}
__device__ __forceinline__ float tanh_(float x) {
    return fmaf(2.0f, rcp_(1.0f + ex2_(-2.8853900817779268f * x)), -1.0f);
}
__device__ __forceinline__ void barhalf(int half) {
    asm volatile("bar.sync %0, 256;" :: "r"(half + 1) : "memory");
}

// no-op kernels: keep ncu's capture slot (-s 5 -c 1) on k_scan (our 4th launch)
__global__ void k_nop() {}

// ---------------------------------------------------------------------------
// K0: proj[v][j] = sg_j * (sum_k emb[v][k] * w_ih_f[j][k] + b_ih_f[j] + b_hh_f[j])
// sg_j = 0.5 for sigmoid gates (i,f,o), 1.0 for candidate gate (g) — the
// sigmoid(x) = 0.5*tanh(0.5x)+0.5 pre-scale baked in at the producer.
// ---------------------------------------------------------------------------
__global__ void __launch_bounds__(256) k_proj(
    const float* __restrict__ emb, const float* __restrict__ w,
    const float* __restrict__ b1, const float* __restrict__ b2)
{
    __shared__ __align__(16) float sh_e[8 * 64];
    const int j = threadIdx.x;

    u64 w2[32];
#pragma unroll
    for (int k2 = 0; k2 < 32; ++k2) {
        float2 wv = *(const float2*)&w[j * 64 + 2 * k2];
        w2[k2] = pack2(wv.x, wv.y);
    }
    const float bias = b1[j] + b2[j];
    const float sg = ((j >> 6) == 2) ? 1.0f : 0.5f;

    const int v0 = blockIdx.x * 8;
#pragma unroll
    for (int i = j; i < 512; i += 256) {
        int r = i >> 6, k = i & 63;
        int v = v0 + r;
        sh_e[i] = (v == 0 || v >= VV) ? 0.0f : emb[v * HH + k];
    }
    __syncthreads();
    const ulonglong2* ep = (const ulonglong2*)sh_e;
#pragma unroll
    for (int r = 0; r < 8; ++r) {
        int v = v0 + r;
        if (v >= VV) break;
        u64 acc = 0ull;
#pragma unroll
        for (int k4 = 0; k4 < 16; ++k4) {
            ulonglong2 ev = ep[r * 16 + k4];
            acc = fma2(w2[2 * k4], ev.x, acc);
            acc = fma2(w2[2 * k4 + 1], ev.y, acc);
        }
        g_proj[(size_t)v * G4 + j] = sg * (hsum2(acc) + bias);
    }
}

// ---------------------------------------------------------------------------
// K2: forward LSTM scan — k-split layout for occupancy.
// 128 CTAs x 512 threads, uniform 1 CTA/SM, 4 warps/SMSP.
// Warps 0-7 = batch row b0, warps 8-15 = b0+1 (independent named barriers).
// Lane octet (l&7): gate = l&3, khalf = (l>>2)&1. Each lane pair (l, l^4)
// shares output pair (j0, j0+1): each lane holds HALF the weight rows
// (k in [kh*32, kh*32+32), 32 regs) and finalizes ONE output (j0+kh) after
// a single u64 shfl_xor combine. Quad shfl-down gate exchange, one barrier
// per step, ping-pong h, branch-free mainloop (padded x, last step peeled).
// ---------------------------------------------------------------------------
__global__ void __launch_bounds__(512, 1) k_scan(
    const int* __restrict__ x, const float* __restrict__ whh)
{
    __shared__ __align__(16) float h_sh[2][2][64];  // [buf][half][unit]
    __shared__ int xs[2][TT + 2];                   // per-row indices, padded
    const int tid = threadIdx.x;
    const int w = tid >> 5, l = tid & 31;
    const int half = w >> 3;               // batch row within CTA
    const int w8 = w & 7;                  // warp within row group
    const int gate = l & 3;                // 0:i 1:f 2:g 3:o
    const int kh = (l >> 2) & 1;           // k-half owned by this lane
    const int q = l >> 3;                  // octet index within warp
    const int u0 = 2 * (w8 * 4 + q);       // even unit 0..62
    const int b = blockIdx.x * 2 + half;
    const int j0 = gate * 64 + u0;
    const int jme = j0 + kh;               // the output this lane finalizes

    // stage x indices for both rows, pad 2 trailing entries (clamp-free loop)
    {
        const int* xr = x + (size_t)(blockIdx.x * 2) * TT;
        for (int i = tid; i < TT; i += 512) {
            xs[0][i] = xr[i];
            xs[1][i] = xr[TT + i];
        }
        if (tid < 4)
            xs[tid >> 1][TT + (tid & 1)] = xr[(tid >> 1) * TT + TT - 1];
    }

    // activation params for jme's gate (same for both kh of a pair)
    const float sg = (gate == 2) ? 1.0f : 0.5f;
    const float mv = (gate == 2) ? 1.0f : 0.5f;
    const float av = (gate == 2) ? 0.0f : 0.5f;

    // half weight rows j0, j0+1 (k-range [kh*32, kh*32+32)), pre-scaled by sg
    u64 wa[16], wb[16];
    {
        const float* wr0 = whh + j0 * 64 + kh * 32;
        const float* wr1 = wr0 + 64;
#pragma unroll
        for (int k2 = 0; k2 < 16; ++k2) {
            float2 va = *(const float2*)&wr0[2 * k2];
            float2 vb = *(const float2*)&wr1[2 * k2];
            wa[k2] = pack2(sg * va.x, sg * va.y);
            wb[k2] = pack2(sg * vb.x, sg * vb.y);
        }
    }

    // zero step-0 read buffer
    if (tid < 128) h_sh[0][tid >> 6][tid & 63] = 0.0f;
    float c = 0.0f;

    const float* __restrict__ proj = g_proj;
    const int* xsh = xs[half];

    __syncthreads();  // x stage + h init visible

    // distance-2 prefetch of input projections (pre-scaled in table)
    float xc = proj[xsh[0] * G4 + jme];
    float xn = proj[xsh[1] * G4 + jme];

    for (int t = 0; t < TT - 1; ++t) {
        float xf = proj[xsh[t + 2] * G4 + jme];   // padded: no clamp

        // half-dot partials for j0 (A) and j0+1 (D)
        const ulonglong2* hp = (const ulonglong2*)(&h_sh[t & 1][half][kh * 32]);
        u64 a0 = 0ull, a1 = 0ull, d0 = 0ull, d1 = 0ull;
#pragma unroll
        for (int k4 = 0; k4 < 8; ++k4) {
            ulonglong2 hv = hp[k4];
            a0 = fma2(wa[2 * k4],     hv.x, a0);
            a1 = fma2(wa[2 * k4 + 1], hv.y, a1);
            d0 = fma2(wb[2 * k4],     hv.x, d0);
            d1 = fma2(wb[2 * k4 + 1], hv.y, d1);
        }
        u64 A = add2(a0, a1);
        u64 D = add2(d0, d1);

        // cross-khalf combine: send the partial I DON'T finalize
        u64 Q = kh ? A : D;
        u64 Qx = __shfl_xor_sync(0xffffffffu, Q, 4);
        u64 P = add2(kh ? D : A, Qx);
        float p = hsum2(P) + xc;

        // one MUFU activation for my output
        float v = fmaf(mv, tanha_(p), av);

        // octet exchange: gate0 lanes (kh0->unit u0, kh1->unit u0+1)
        float f = __shfl_down_sync(0xffffffffu, v, 1);
        float g = __shfl_down_sync(0xffffffffu, v, 2);
        float o = __shfl_down_sync(0xffffffffu, v, 3);

        // unconditional cell update (garbage off-lanes, never stored)
        c = f * c + v * g;
        float hnew = o * tanha_(c);
        if (gate == 0)                       // predicated STS.32
            h_sh[(t + 1) & 1][half][u0 + kh] = hnew;
        barhalf(half);

        xc = xn; xn = xf;
    }

    // peeled final step t = TT-1: write h straight to global
    {
        const ulonglong2* hp = (const ulonglong2*)(&h_sh[(TT - 1) & 1][half][kh * 32]);
        u64 a0 = 0ull, a1 = 0ull, d0 = 0ull, d1 = 0ull;
#pragma unroll
        for (int k4 = 0; k4 < 8; ++k4) {
            ulonglong2 hv = hp[k4];
            a0 = fma2(wa[2 * k4],     hv.x, a0);
            a1 = fma2(wa[2 * k4 + 1], hv.y, a1);
            d0 = fma2(wb[2 * k4],     hv.x, d0);
            d1 = fma2(wb[2 * k4 + 1], hv.y, d1);
        }
        u64 A = add2(a0, a1);
        u64 D = add2(d0, d1);
        u64 Q = kh ? A : D;
        u64 Qx = __shfl_xor_sync(0xffffffffu, Q, 4);
        u64 P = add2(kh ? D : A, Qx);
        float p = hsum2(P) + xc;
        float v = fmaf(mv, tanha_(p), av);
        float f = __shfl_down_sync(0xffffffffu, v, 1);
        float g = __shfl_down_sync(0xffffffffu, v, 2);
        float o = __shfl_down_sync(0xffffffffu, v, 3);
        c = f * c + v * g;
        float hnew = o * tanha_(c);
        if (gate == 0)
            g_hf[b * HH + u0 + kh] = hnew;
    }
}

// ---------------------------------------------------------------------------
// K3: fused tail. One block per batch row:
//   1) backward LSTM single step (hs_b[0]) from zero state at t=T-1
//   2) fc: out[b][c] = concat(hf[b], hb[b]) . w_fc[c] + b_fc[c]
// ---------------------------------------------------------------------------
__global__ void __launch_bounds__(256) k_tail(
    const int* __restrict__ x, const float* __restrict__ emb,
    const float* __restrict__ w, const float* __restrict__ b1,
    const float* __restrict__ b2, const float* __restrict__ wfc,
    const float* __restrict__ bfc, float* __restrict__ out)
{
    __shared__ __align__(16) float e_sh[64];
    __shared__ float g_sh[256];
    __shared__ float hb_sh[64];
    const int j = threadIdx.x;
    const int b = blockIdx.x;

    if (j < 64) {
        int idx = x[b * TT + (TT - 1)];
        e_sh[j] = (idx == 0) ? 0.0f : emb[idx * HH + j];
    }
    __syncthreads();

    float acc = b1[j] + b2[j];
    const ulonglong2* ep = (const ulonglong2*)e_sh;
    u64 a2 = 0ull;
#pragma unroll
    for (int k4 = 0; k4 < 16; ++k4) {
        float2 wv0 = *(const float2*)&w[j * 64 + 4 * k4];
        float2 wv1 = *(const float2*)&w[j * 64 + 4 * k4 + 2];
        ulonglong2 ev = ep[k4];
        a2 = fma2(pack2(wv0.x, wv0.y), ev.x, a2);
        a2 = fma2(pack2(wv1.x, wv1.y), ev.y, a2);
    }
    acc += hsum2(a2);

    const int gate = j >> 6;
    g_sh[j] = (gate == 2) ? tanh_(acc) : sigmoid_(acc);
    __syncthreads();

    if (j < 64) {
        float iv = g_sh[j];
        float gv = g_sh[128 + j];
        float ov = g_sh[192 + j];
        float cc = iv * gv;               // f*c0 = 0
        hb_sh[j] = ov * tanh_(cc);
    }
    __syncthreads();

    if (j < 12) {
        float s = bfc[j];
        const float* hf = g_hf + b * HH;
#pragma unroll
        for (int k = 0; k < 64; ++k)
            s += hf[k] * wfc[j * 128 + k];
#pragma unroll
        for (int k = 0; k < 64; ++k)
            s += hb_sh[k] * wfc[j * 128 + 64 + k];
        out[b * 12 + j] = s;
    }
}

// ---------------------------------------------------------------------------
extern "C" void kernel_launch(void* const* d_in, const int* in_sizes, int n_in,
                              void* d_out, int out_size)
{
    const int*   x      = (const int*)d_in[0];
    const float* emb    = (const float*)d_in[1];
    const float* w_ih_f = (const float*)d_in[2];
    const float* w_hh_f = (const float*)d_in[3];
    const float* b_ih_f = (const float*)d_in[4];
    const float* b_hh_f = (const float*)d_in[5];
    const float* w_ih_b = (const float*)d_in[6];
    const float* w_hh_b = (const float*)d_in[7];
    const float* b_ih_b = (const float*)d_in[8];
    const float* b_hh_b = (const float*)d_in[9];
    const float* w_fc   = (const float*)d_in[10];
    const float* b_fc   = (const float*)d_in[11];
    float* out = (float*)d_out;

    k_proj<<<(VV + 7) / 8, 256>>>(emb, w_ih_f, b_ih_f, b_hh_f);
    k_nop<<<1, 32>>>();   // slot alignment: keep k_scan as our 4th launch
    k_nop<<<1, 32>>>();   // so ncu (-s 5 -c 1) captures it
    k_scan<<<BB / 2, 512>>>(x, w_hh_f);
    k_tail<<<BB, 256>>>(x, emb, w_ih_b, b_ih_b, b_hh_b, w_fc, b_fc, out);
}

// round 10
// speedup vs baseline: 1.3074x; 1.3074x over previous
#include <cuda_runtime.h>

// Problem constants
#define BB 256      // batch
#define TT 2000     // seq len
#define HH 64       // hidden
#define G4 256      // 4*H
#define VV 2000     // vocab

// Scratch (allocation-free rule: __device__ globals)
__device__ float g_proj[(size_t)VV * G4];   // [v][j] fp32 (gate-prescaled), 2 MB
__device__ float g_hf[BB * HH];

typedef unsigned long long u64;

__device__ __forceinline__ u64 fma2(u64 a, u64 b, u64 c) {
    u64 d;
    asm("fma.rn.f32x2 %0, %1, %2, %3;" : "=l"(d) : "l"(a), "l"(b), "l"(c));
    return d;
}
__device__ __forceinline__ u64 add2(u64 a, u64 b) {
    u64 d;
    asm("add.rn.f32x2 %0, %1, %2;" : "=l"(d) : "l"(a), "l"(b));
    return d;
}
__device__ __forceinline__ u64 pack2(float lo, float hi) {
    u64 d;
    asm("mov.b64 %0, {%1, %2};" : "=l"(d) : "f"(lo), "f"(hi));
    return d;
}
__device__ __forceinline__ float hsum2(u64 a) {
    float lo, hi;
    asm("mov.b64 {%0, %1}, %2;" : "=f"(lo), "=f"(hi) : "l"(a));
    return lo + hi;
}
__device__ __forceinline__ float ex2_(float x) {
    float r; asm("ex2.approx.f32 %0, %1;" : "=f"(r) : "f"(x)); return r;
}
__device__ __forceinline__ float rcp_(float x) {
    float r; asm("rcp.approx.f32 %0, %1;" : "=f"(r) : "f"(x)); return r;
}
__device__ __forceinline__ float tanha_(float x) {
    float r; asm("tanh.approx.f32 %0, %1;" : "=f"(r) : "f"(x)); return r;
}
__device__ __forceinline__ float sigmoid_(float x) {
    return rcp_(1.0f + ex2_(-1.4426950408889634f * x));
}
__device__ __forceinline__ float tanh_(float x) {
    return fmaf(2.0f, rcp_(1.0f + ex2_(-2.8853900817779268f * x)), -1.0f);
}

// no-op kernels: keep ncu's capture slot (-s 5 -c 1) on k_scan (our 4th launch)
__global__ void k_nop() {}

// ---------------------------------------------------------------------------
// K0: proj[v][j] = sg_j * (sum_k emb[v][k] * w_ih_f[j][k] + b_ih_f[j] + b_hh_f[j])
// sg_j = 0.5 for sigmoid gates (i,f,o), 1.0 for candidate gate (g).
// ---------------------------------------------------------------------------
__global__ void __launch_bounds__(256) k_proj(
    const float* __restrict__ emb, const float* __restrict__ w,
    const float* __restrict__ b1, const float* __restrict__ b2)
{
    __shared__ __align__(16) float sh_e[8 * 64];
    const int j = threadIdx.x;

    u64 w2[32];
#pragma unroll
    for (int k2 = 0; k2 < 32; ++k2) {
        float2 wv = *(const float2*)&w[j * 64 + 2 * k2];
        w2[k2] = pack2(wv.x, wv.y);
    }
    const float bias = b1[j] + b2[j];
    const float sg = ((j >> 6) == 2) ? 1.0f : 0.5f;

    const int v0 = blockIdx.x * 8;
#pragma unroll
    for (int i = j; i < 512; i += 256) {
        int r = i >> 6, k = i & 63;
        int v = v0 + r;
        sh_e[i] = (v == 0 || v >= VV) ? 0.0f : emb[v * HH + k];
    }
    __syncthreads();
    const ulonglong2* ep = (const ulonglong2*)sh_e;
#pragma unroll
    for (int r = 0; r < 8; ++r) {
        int v = v0 + r;
        if (v >= VV) break;
        u64 acc = 0ull;
#pragma unroll
        for (int k4 = 0; k4 < 16; ++k4) {
            ulonglong2 ev = ep[r * 16 + k4];
            acc = fma2(w2[2 * k4], ev.x, acc);
            acc = fma2(w2[2 * k4 + 1], ev.y, acc);
        }
        g_proj[(size_t)v * G4 + j] = sg * (hsum2(acc) + bias);
    }
}

// ---------------------------------------------------------------------------
// K2: forward LSTM scan — two batch rows per THREAD (weights shared).
// 128 CTAs x 128 threads; each CTA owns rows (2b, 2b+1). Thread owns
// adjacent outputs (j0, j0+1) for BOTH rows: 4 independent 64-dots per step
// (two independent row-chains inside each warp hide each other's tails).
// Quad-gate lanes, shfl gate exchange, ONE __syncthreads per step serving
// both rows, ping-pong h buffers, branch-free mainloop (padded x, peeled
// last step), tanh.approx activations, sigmoid pre-scale in proj/weights.
// ---------------------------------------------------------------------------
__global__ void __launch_bounds__(128, 1) k_scan(
    const int* __restrict__ x, const float* __restrict__ whh)
{
    __shared__ __align__(16) float h_sh[2][2][64];  // [buf][row][unit]
    __shared__ int xs[2][TT + 2];                   // per-row indices, padded
    const int tid = threadIdx.x;
    const int w = tid >> 5, l = tid & 31;
    const int gate = l & 3;                // 0:i 1:f 2:g 3:o
    const int u0 = 2 * (w * 8 + (l >> 2)); // even unit 0..62
    const int b0 = blockIdx.x * 2;
    const int j0 = gate * 64 + u0;         // adjacent pair j0, j0+1

    // stage x indices for both rows, pad 2 trailing entries (clamp-free)
    {
        const int* xr = x + (size_t)b0 * TT;
        for (int i = tid; i < TT; i += 128) {
            xs[0][i] = xr[i];
            xs[1][i] = xr[TT + i];
        }
        if (tid < 4)
            xs[tid >> 1][TT + (tid & 1)] = xr[(tid >> 1) * TT + TT - 1];
    }

    const float sg = (gate == 2) ? 1.0f : 0.5f;
    const float mv = (gate == 2) ? 1.0f : 0.5f;
    const float av = (gate == 2) ? 0.0f : 0.5f;

    // weight rows j0, j0+1 in registers (k-packed f32x2), pre-scaled by sg
    u64 wa[32], wb[32];
#pragma unroll
    for (int k2 = 0; k2 < 32; ++k2) {
        float2 va = *(const float2*)&whh[j0 * 64 + 2 * k2];
        float2 vb = *(const float2*)&whh[(j0 + 1) * 64 + 2 * k2];
        wa[k2] = pack2(sg * va.x, sg * va.y);
        wb[k2] = pack2(sg * vb.x, sg * vb.y);
    }

    // zero step-0 read buffers (both rows)
    h_sh[0][tid >> 6][tid & 63] = 0.0f;
    float c00 = 0.0f, c01 = 0.0f, c10 = 0.0f, c11 = 0.0f;

    const float* __restrict__ proj = g_proj;

    __syncthreads();  // x stage + h init visible

    // distance-2 prefetch, both rows (pre-scaled in table)
    float2 xc0 = *(const float2*)&proj[xs[0][0] * G4 + j0];
    float2 xc1 = *(const float2*)&proj[xs[1][0] * G4 + j0];
    float2 xn0 = *(const float2*)&proj[xs[0][1] * G4 + j0];
    float2 xn1 = *(const float2*)&proj[xs[1][1] * G4 + j0];

#pragma unroll 2
    for (int t = 0; t < TT - 1; ++t) {
        float2 xf0 = *(const float2*)&proj[xs[0][t + 2] * G4 + j0];
        float2 xf1 = *(const float2*)&proj[xs[1][t + 2] * G4 + j0];

        const ulonglong2* hp0 = (const ulonglong2*)h_sh[t & 1][0];
        const ulonglong2* hp1 = (const ulonglong2*)h_sh[t & 1][1];
        // 4 dots: (row0:j0)=A, (row0:j0+1)=B, (row1:j0)=C, (row1:j0+1)=D
        u64 A0 = 0ull, A1 = 0ull, A2 = 0ull, A3 = 0ull;
        u64 B0 = 0ull, B1 = 0ull, B2 = 0ull, B3 = 0ull;
        u64 C0 = 0ull, C1 = 0ull, C2 = 0ull, C3 = 0ull;
        u64 D0 = 0ull, D1 = 0ull, D2 = 0ull, D3 = 0ull;
#pragma unroll
        for (int k4 = 0; k4 < 8; ++k4) {
            ulonglong2 hv0 = hp0[k4];
            ulonglong2 hw0 = hp0[8 + k4];
            ulonglong2 hv1 = hp1[k4];
            ulonglong2 hw1 = hp1[8 + k4];
            A0 = fma2(wa[2 * k4],      hv0.x, A0);
            A1 = fma2(wa[2 * k4 + 1],  hv0.y, A1);
            A2 = fma2(wa[16 + 2 * k4], hw0.x, A2);
            A3 = fma2(wa[17 + 2 * k4], hw0.y, A3);
            B0 = fma2(wb[2 * k4],      hv0.x, B0);
            B1 = fma2(wb[2 * k4 + 1],  hv0.y, B1);
            B2 = fma2(wb[16 + 2 * k4], hw0.x, B2);
            B3 = fma2(wb[17 + 2 * k4], hw0.y, B3);
            C0 = fma2(wa[2 * k4],      hv1.x, C0);
            C1 = fma2(wa[2 * k4 + 1],  hv1.y, C1);
            C2 = fma2(wa[16 + 2 * k4], hw1.x, C2);
            C3 = fma2(wa[17 + 2 * k4], hw1.y, C3);
            D0 = fma2(wb[2 * k4],      hv1.x, D0);
            D1 = fma2(wb[2 * k4 + 1],  hv1.y, D1);
            D2 = fma2(wb[16 + 2 * k4], hw1.x, D2);
            D3 = fma2(wb[17 + 2 * k4], hw1.y, D3);
        }
        float p00 = hsum2(add2(add2(A0, A1), add2(A2, A3))) + xc0.x;
        float p01 = hsum2(add2(add2(B0, B1), add2(B2, B3))) + xc0.y;
        float p10 = hsum2(add2(add2(C0, C1), add2(C2, C3))) + xc1.x;
        float p11 = hsum2(add2(add2(D0, D1), add2(D2, D3))) + xc1.y;

        float v00 = fmaf(mv, tanha_(p00), av);
        float v01 = fmaf(mv, tanha_(p01), av);
        float v10 = fmaf(mv, tanha_(p10), av);
        float v11 = fmaf(mv, tanha_(p11), av);

        // quad exchange per output (gate0 lanes receive f,g,o)
        float f00 = __shfl_down_sync(0xffffffffu, v00, 1);
        float g00 = __shfl_down_sync(0xffffffffu, v00, 2);
        float o00 = __shfl_down_sync(0xffffffffu, v00, 3);
        float f01 = __shfl_down_sync(0xffffffffu, v01, 1);
        float g01 = __shfl_down_sync(0xffffffffu, v01, 2);
        float o01 = __shfl_down_sync(0xffffffffu, v01, 3);
        float f10 = __shfl_down_sync(0xffffffffu, v10, 1);
        float g10 = __shfl_down_sync(0xffffffffu, v10, 2);
        float o10 = __shfl_down_sync(0xffffffffu, v10, 3);
        float f11 = __shfl_down_sync(0xffffffffu, v11, 1);
        float g11 = __shfl_down_sync(0xffffffffu, v11, 2);
        float o11 = __shfl_down_sync(0xffffffffu, v11, 3);

        // unconditional cell updates (garbage off-lanes never stored)
        c00 = f00 * c00 + v00 * g00;
        c01 = f01 * c01 + v01 * g01;
        c10 = f10 * c10 + v10 * g10;
        c11 = f11 * c11 + v11 * g11;
        float2 h0; h0.x = o00 * tanha_(c00); h0.y = o01 * tanha_(c01);
        float2 h1; h1.x = o10 * tanha_(c10); h1.y = o11 * tanha_(c11);
        if (gate == 0) {                     // predicated STS.64 x2
            *(float2*)&h_sh[(t + 1) & 1][0][u0] = h0;
            *(float2*)&h_sh[(t + 1) & 1][1][u0] = h1;
        }
        __syncthreads();

        xc0 = xn0; xc1 = xn1; xn0 = xf0; xn1 = xf1;
    }

    // peeled final step t = TT-1: write h straight to global
    {
        const ulonglong2* hp0 = (const ulonglong2*)h_sh[(TT - 1) & 1][0];
        const ulonglong2* hp1 = (const ulonglong2*)h_sh[(TT - 1) & 1][1];
        u64 A0 = 0ull, A1 = 0ull, A2 = 0ull, A3 = 0ull;
        u64 B0 = 0ull, B1 = 0ull, B2 = 0ull, B3 = 0ull;
        u64 C0 = 0ull, C1 = 0ull, C2 = 0ull, C3 = 0ull;
        u64 D0 = 0ull, D1 = 0ull, D2 = 0ull, D3 = 0ull;
#pragma unroll
        for (int k4 = 0; k4 < 8; ++k4) {
            ulonglong2 hv0 = hp0[k4];
            ulonglong2 hw0 = hp0[8 + k4];
            ulonglong2 hv1 = hp1[k4];
            ulonglong2 hw1 = hp1[8 + k4];
            A0 = fma2(wa[2 * k4],      hv0.x, A0);
            A1 = fma2(wa[2 * k4 + 1],  hv0.y, A1);
            A2 = fma2(wa[16 + 2 * k4], hw0.x, A2);
            A3 = fma2(wa[17 + 2 * k4], hw0.y, A3);
            B0 = fma2(wb[2 * k4],      hv0.x, B0);
            B1 = fma2(wb[2 * k4 + 1],  hv0.y, B1);
            B2 = fma2(wb[16 + 2 * k4], hw0.x, B2);
            B3 = fma2(wb[17 + 2 * k4], hw0.y, B3);
            C0 = fma2(wa[2 * k4],      hv1.x, C0);
            C1 = fma2(wa[2 * k4 + 1],  hv1.y, C1);
            C2 = fma2(wa[16 + 2 * k4], hw1.x, C2);
            C3 = fma2(wa[17 + 2 * k4], hw1.y, C3);
            D0 = fma2(wb[2 * k4],      hv1.x, D0);
            D1 = fma2(wb[2 * k4 + 1],  hv1.y, D1);
            D2 = fma2(wb[16 + 2 * k4], hw1.x, D2);
            D3 = fma2(wb[17 + 2 * k4], hw1.y, D3);
        }
        float p00 = hsum2(add2(add2(A0, A1), add2(A2, A3))) + xc0.x;
        float p01 = hsum2(add2(add2(B0, B1), add2(B2, B3))) + xc0.y;
        float p10 = hsum2(add2(add2(C0, C1), add2(C2, C3))) + xc1.x;
        float p11 = hsum2(add2(add2(D0, D1), add2(D2, D3))) + xc1.y;
        float v00 = fmaf(mv, tanha_(p00), av);
        float v01 = fmaf(mv, tanha_(p01), av);
        float v10 = fmaf(mv, tanha_(p10), av);
        float v11 = fmaf(mv, tanha_(p11), av);
        float f00 = __shfl_down_sync(0xffffffffu, v00, 1);
        float g00 = __shfl_down_sync(0xffffffffu, v00, 2);
        float o00 = __shfl_down_sync(0xffffffffu, v00, 3);
        float f01 = __shfl_down_sync(0xffffffffu, v01, 1);
        float g01 = __shfl_down_sync(0xffffffffu, v01, 2);
        float o01 = __shfl_down_sync(0xffffffffu, v01, 3);
        float f10 = __shfl_down_sync(0xffffffffu, v10, 1);
        float g10 = __shfl_down_sync(0xffffffffu, v10, 2);
        float o10 = __shfl_down_sync(0xffffffffu, v10, 3);
        float f11 = __shfl_down_sync(0xffffffffu, v11, 1);
        float g11 = __shfl_down_sync(0xffffffffu, v11, 2);
        float o11 = __shfl_down_sync(0xffffffffu, v11, 3);
        c00 = f00 * c00 + v00 * g00;
        c01 = f01 * c01 + v01 * g01;
        c10 = f10 * c10 + v10 * g10;
        c11 = f11 * c11 + v11 * g11;
        if (gate == 0) {
            float2 h0; h0.x = o00 * tanha_(c00); h0.y = o01 * tanha_(c01);
            float2 h1; h1.x = o10 * tanha_(c10); h1.y = o11 * tanha_(c11);
            *(float2*)&g_hf[b0 * HH + u0] = h0;
            *(float2*)&g_hf[(b0 + 1) * HH + u0] = h1;
        }
    }
}

// ---------------------------------------------------------------------------
// K3: fused tail. One block per batch row:
//   1) backward LSTM single step (hs_b[0]) from zero state at t=T-1
//   2) fc: out[b][c] = concat(hf[b], hb[b]) . w_fc[c] + b_fc[c]
// ---------------------------------------------------------------------------
__global__ void __launch_bounds__(256) k_tail(
    const int* __restrict__ x, const float* __restrict__ emb,
    const float* __restrict__ w, const float* __restrict__ b1,
    const float* __restrict__ b2, const float* __restrict__ wfc,
    const float* __restrict__ bfc, float* __restrict__ out)
{
    __shared__ __align__(16) float e_sh[64];
    __shared__ float g_sh[256];
    __shared__ float hb_sh[64];
    const int j = threadIdx.x;
    const int b = blockIdx.x;

    if (j < 64) {
        int idx = x[b * TT + (TT - 1)];
        e_sh[j] = (idx == 0) ? 0.0f : emb[idx * HH + j];
    }
    __syncthreads();

    float acc = b1[j] + b2[j];
    const ulonglong2* ep = (const ulonglong2*)e_sh;
    u64 a2 = 0ull;
#pragma unroll
    for (int k4 = 0; k4 < 16; ++k4) {
        float2 wv0 = *(const float2*)&w[j * 64 + 4 * k4];
        float2 wv1 = *(const float2*)&w[j * 64 + 4 * k4 + 2];
        ulonglong2 ev = ep[k4];
        a2 = fma2(pack2(wv0.x, wv0.y), ev.x, a2);
        a2 = fma2(pack2(wv1.x, wv1.y), ev.y, a2);
    }
    acc += hsum2(a2);

    const int gate = j >> 6;
    g_sh[j] = (gate == 2) ? tanh_(acc) : sigmoid_(acc);
    __syncthreads();

    if (j < 64) {
        float iv = g_sh[j];
        float gv = g_sh[128 + j];
        float ov = g_sh[192 + j];
        float cc = iv * gv;               // f*c0 = 0
        hb_sh[j] = ov * tanh_(cc);
    }
    __syncthreads();

    if (j < 12) {
        float s = bfc[j];
        const float* hf = g_hf + b * HH;
#pragma unroll
        for (int k = 0; k < 64; ++k)
            s += hf[k] * wfc[j * 128 + k];
#pragma unroll
        for (int k = 0; k < 64; ++k)
            s += hb_sh[k] * wfc[j * 128 + 64 + k];
        out[b * 12 + j] = s;
    }
}

// ---------------------------------------------------------------------------
extern "C" void kernel_launch(void* const* d_in, const int* in_sizes, int n_in,
                              void* d_out, int out_size)
{
    const int*   x      = (const int*)d_in[0];
    const float* emb    = (const float*)d_in[1];
    const float* w_ih_f = (const float*)d_in[2];
    const float* w_hh_f = (const float*)d_in[3];
    const float* b_ih_f = (const float*)d_in[4];
    const float* b_hh_f = (const float*)d_in[5];
    const float* w_ih_b = (const float*)d_in[6];
    const float* w_hh_b = (const float*)d_in[7];
    const float* b_ih_b = (const float*)d_in[8];
    const float* b_hh_b = (const float*)d_in[9];
    const float* w_fc   = (const float*)d_in[10];
    const float* b_fc   = (const float*)d_in[11];
    float* out = (float*)d_out;

    k_proj<<<(VV + 7) / 8, 256>>>(emb, w_ih_f, b_ih_f, b_hh_f);
    k_nop<<<1, 32>>>();   // slot alignment: keep k_scan as our 4th launch
    k_nop<<<1, 32>>>();   // so ncu (-s 5 -c 1) captures it
    k_scan<<<BB / 2, 128>>>(x, w_hh_f);
    k_tail<<<BB, 256>>>(x, emb, w_ih_b, b_ih_b, b_hh_b, w_fc, b_fc, out);
}